// round 15
// baseline (speedup 1.0000x reference)
#include <cuda_runtime.h>
#include <math.h>

// Problem constants
#define BB 128
#define NN 2000
#define CC 100
#define DD 128
#define HH 8
#define NEGV (-1000000000.0f)
#define CLIPV 10.0f

#define SPLIT 20
#define CH (NN / SPLIT)       // 100 nodes per chunk
#define PRE_CTAS 96           // weight-folding CTAs (placed first in grid)
#define FOLD_ROWS 768         // PQ:0..383  Zt:384..511  ZV:512..639  ZW:640..767

// Output layout (float32, flattened tuple order)
#define OUT_AUG 0
#define OUT_GEMB 65536
#define OUT_GUID 81920
#define OUT_CLU 82048

// Global scratch
#define G2OFF (BB * SPLIT * DD)
__device__ float g_part[2 * BB * SPLIT * DD];   // partial masked sums
__device__ float g_fold[FOLD_ROWS * DD];        // folded weight products
__device__ float g_u[BB * 1024];                // u packed per batch (i*8+h)
__device__ float g_m2s[BB * DD];                // mean2 per batch
__device__ float g_vcmf[BB * 104];              // adjusted vcm per batch

// ---- sniff helper: ONE barrier ----
__device__ __forceinline__ int sniff_flag(const void* maskp, int t) {
    unsigned wword = ((const unsigned*)maskp)[t];
    int contrib = ((wword & 0x0000ff00u) ? 1 : 0) | ((wword & 0xffff0000u) ? 2 : 0);
    int oo = __syncthreads_or(contrib);
    return (oo & 1) ? 0 : ((oo & 2) ? 2 : 1);
}

__device__ __forceinline__ bool rdmask(const void* p, int flag, long long i) {
    if (flag == 0) return ((const unsigned char*)p)[i] != 0;
    if (flag == 1) return ((const int*)p)[i] != 0;
    return ((const float*)p)[i] != 0.0f;
}

// ============================================================================
// Kernel 1: [blocks 0..95] weight folding  +  [blocks 96..] masked partial
// sums over node_embeddings. grid = PRE_CTAS + B*SPLIT.
// ============================================================================
__global__ void __launch_bounds__(256)
means_pre_kernel(const float* __restrict__ node, const void* __restrict__ maskp,
                 const void* __restrict__ cmaskp,
                 const float* __restrict__ Wq, const float* __restrict__ Wk,
                 const float* __restrict__ Wv, const float* __restrict__ Wks,
                 const float* __restrict__ Wmq, const float* __restrict__ Wmk,
                 const float* __restrict__ Wmv, const float* __restrict__ Wmo) {
    __shared__ float red[2 * 1024];
    __shared__ float a_sm[8 * 128];
    __shared__ unsigned char mloc[CH], cmloc[CH];
    const int t = threadIdx.x;
    const int lane = t & 31;
    const int w = t >> 5;

    const int flag = sniff_flag(maskp, t);

    if (blockIdx.x < PRE_CTAS) {
        const int r0 = blockIdx.x * 8;
        for (int idx = t; idx < 8 * 128; idx += 256) {
            int row = idx >> 7, j = idx & 127;
            int R = r0 + row;
            const float* A;
            if (R < 384)      A = Wq  + (size_t)R * DD;
            else if (R < 512) A = Wk  + (size_t)(R - 384) * DD;
            else if (R < 640) A = Wv  + (size_t)(R - 512) * DD;
            else              A = Wmo + (size_t)(R - 640) * DD;
            a_sm[idx] = A[j];
        }
        __syncthreads();
        const int col = t & 127, rr = t >> 7;
        float a0 = 0.f, a1 = 0.f, a2 = 0.f, a3 = 0.f;
        if (r0 < 640) {
            const float* Bm = (r0 < 384) ? Wmq : (r0 < 512) ? Wmk : Wmv;
#pragma unroll 8
            for (int j = 0; j < DD; j++) {
                float bv = Bm[j * DD + col];
                a0 = fmaf(a_sm[(rr + 0) * DD + j], bv, a0);
                a1 = fmaf(a_sm[(rr + 2) * DD + j], bv, a1);
                a2 = fmaf(a_sm[(rr + 4) * DD + j], bv, a2);
                a3 = fmaf(a_sm[(rr + 6) * DD + j], bv, a3);
            }
        } else {
            // ZW[m][i] = sum_j Wmo[m][j] * Wks[i][j]; col = i
#pragma unroll 4
            for (int j = 0; j < DD; j += 4) {
                float4 wv = *(const float4*)(Wks + (size_t)col * DD + j);
                a0 = fmaf(a_sm[(rr + 0) * DD + j],     wv.x, a0);
                a0 = fmaf(a_sm[(rr + 0) * DD + j + 1], wv.y, a0);
                a0 = fmaf(a_sm[(rr + 0) * DD + j + 2], wv.z, a0);
                a0 = fmaf(a_sm[(rr + 0) * DD + j + 3], wv.w, a0);
                a1 = fmaf(a_sm[(rr + 2) * DD + j],     wv.x, a1);
                a1 = fmaf(a_sm[(rr + 2) * DD + j + 1], wv.y, a1);
                a1 = fmaf(a_sm[(rr + 2) * DD + j + 2], wv.z, a1);
                a1 = fmaf(a_sm[(rr + 2) * DD + j + 3], wv.w, a1);
                a2 = fmaf(a_sm[(rr + 4) * DD + j],     wv.x, a2);
                a2 = fmaf(a_sm[(rr + 4) * DD + j + 1], wv.y, a2);
                a2 = fmaf(a_sm[(rr + 4) * DD + j + 2], wv.z, a2);
                a2 = fmaf(a_sm[(rr + 4) * DD + j + 3], wv.w, a2);
                a3 = fmaf(a_sm[(rr + 6) * DD + j],     wv.x, a3);
                a3 = fmaf(a_sm[(rr + 6) * DD + j + 1], wv.y, a3);
                a3 = fmaf(a_sm[(rr + 6) * DD + j + 2], wv.z, a3);
                a3 = fmaf(a_sm[(rr + 6) * DD + j + 3], wv.w, a3);
            }
        }
        if (r0 >= 384 && r0 < 512) {
            // Z region: store TRANSPOSED (Zt[k][i]); k = col, i = output row
            int ib = r0 - 384 + rr;
            float* zt = g_fold + (size_t)(384 + col) * DD;
            zt[ib + 0] = a0;
            zt[ib + 2] = a1;
            zt[ib + 4] = a2;
            zt[ib + 6] = a3;
        } else {
            g_fold[(size_t)(r0 + rr + 0) * DD + col] = a0;
            g_fold[(size_t)(r0 + rr + 2) * DD + col] = a1;
            g_fold[(size_t)(r0 + rr + 4) * DD + col] = a2;
            g_fold[(size_t)(r0 + rr + 6) * DD + col] = a3;
        }
        return;
    }

    // ---------------- means path ----------------
    const int bs = blockIdx.x - PRE_CTAS;
    const int b = bs / SPLIT;
    const int s = bs % SPLIT;

    const long long mbase = (long long)b * NN + s * CH;
    for (int n = t; n < CH; n += 256) {
        mloc[n]  = rdmask(maskp,  flag, mbase + n) ? 1 : 0;
        cmloc[n] = rdmask(cmaskp, flag, mbase + n) ? 1 : 0;
    }
    __syncthreads();

    const float* np_ = node + ((size_t)b * NN + (size_t)s * CH) * DD;
    const int d0 = lane * 4;
    float4 a1 = make_float4(0.f, 0.f, 0.f, 0.f);
    float4 a2 = make_float4(0.f, 0.f, 0.f, 0.f);
#pragma unroll 6
    for (int n = w; n < CH; n += 8) {
        float4 v = __ldcs((const float4*)(np_ + (size_t)n * DD + d0));
        bool m = mloc[n] != 0;
        bool mc = (mloc[n] | cmloc[n]) != 0;
        if (!m)  { a1.x += v.x; a1.y += v.y; a1.z += v.z; a1.w += v.w; }
        if (!mc) { a2.x += v.x; a2.y += v.y; a2.z += v.z; a2.w += v.w; }
    }
    int o = w * 128 + d0;
    red[o] = a1.x; red[o + 1] = a1.y; red[o + 2] = a1.z; red[o + 3] = a1.w;
    red[1024 + o] = a2.x; red[1024 + o + 1] = a2.y;
    red[1024 + o + 2] = a2.z; red[1024 + o + 3] = a2.w;
    __syncthreads();
    if (t < DD) {
        float s1 = 0.f, s2 = 0.f;
#pragma unroll
        for (int ww = 0; ww < 8; ww++) {
            s1 += red[ww * 128 + t];
            s2 += red[1024 + ww * 128 + t];
        }
        size_t idx = (size_t)(b * SPLIT + s) * DD + t;
        g_part[idx] = s1;
        g_part[G2OFF + idx] = s2;
    }
}

// ============================================================================
// Kernel 2a: global-latency front: means reduce, cluster load, qh (PQ),
// u (Zt). Writes g_u / g_vcmf / g_m2s. grid = B, block = 512.
// ============================================================================
#define A_CS   0        // cluster tile [100][129]
#define A_PB   12900    // warp partials [16][132]
#define A_CTX  15012    // [384]
#define A_VCM  15396    // [104]
#define A_FLOATS 15500
#define A_BYTES (A_FLOATS * 4)

__global__ void __launch_bounds__(512, 1)
clu_front_kernel(const float* __restrict__ depot, const float* __restrict__ cluster,
                 const float* __restrict__ curE,
                 const void* __restrict__ isnewp,
                 const void* __restrict__ vcmp, const void* __restrict__ maskp) {
    extern __shared__ float sm[];
    const int b = blockIdx.x;
    const int t = threadIdx.x;
    const int lane = t & 31;
    const int w = t >> 5;
    const int c4 = lane * 4;

    const int flag = sniff_flag(maskp, t);
    const bool isnew = rdmask(isnewp, flag, b);

    // ===== P0: means reduce (t<128), ctx build, vcm, cluster tile ===========
    if (t < DD) {
        float s1 = 0.f, s2 = 0.f;
#pragma unroll
        for (int s = 0; s < SPLIT; s++) {
            size_t idx = (size_t)(b * SPLIT + s) * DD + t;
            s1 += g_part[idx];
            s2 += g_part[G2OFF + idx];
        }
        float cu = curE[b * DD + t];
        float de = depot[b * DD + t];
        g_m2s[b * DD + t] = s2 * (1.0f / NN);
        sm[A_CTX + t] = s1 * (1.0f / NN);
        sm[A_CTX + 128 + t] = cu;
        sm[A_CTX + 256 + t] = de;
    }
    if (t < CC) sm[A_VCM + t] = rdmask(vcmp, flag, (long long)b * CC + t) ? 1.0f : 0.0f;
    {
        const float* cp = cluster + (size_t)b * CC * DD;
        for (int p4 = t; p4 < (CC * DD) / 4; p4 += 512) {
            float4 v = ((const float4*)cp)[p4];
            int base = p4 * 4;
            float* dst = sm + A_CS + (base >> 7) * 129 + (base & 127);
            dst[0] = v.x; dst[1] = v.y; dst[2] = v.z; dst[3] = v.w;
        }
    }
    __syncthreads();

    // ===== P1: qh partials — warp w takes 24 rows of PQ =====================
    {
        float4 acc = make_float4(0.f, 0.f, 0.f, 0.f);
        int r0 = w * 24;
#pragma unroll 6
        for (int r = r0; r < r0 + 24; r++) {
            float4 pv = *(const float4*)(g_fold + (size_t)r * DD + c4);
            float cx = sm[A_CTX + r];
            acc.x = fmaf(cx, pv.x, acc.x);
            acc.y = fmaf(cx, pv.y, acc.y);
            acc.z = fmaf(cx, pv.z, acc.z);
            acc.w = fmaf(cx, pv.w, acc.w);
        }
        *(float4*)(sm + A_PB + w * 132 + c4) = acc;
        if (w == 15) {  // vcm[0] adjustment
            bool ok = true;
            for (int c = 1 + lane; c < CC; c += 32) ok = ok && (sm[A_VCM + c] != 0.0f);
            bool allv = __all_sync(0xffffffffu, ok);
            if (lane == 0 && isnew) sm[A_VCM + 0] = allv ? 0.0f : 1.0f;
        }
    }
    __syncthreads();

    // ===== P3: warps 0-7: warp-local QH reduce + u from Zt -> g_u ===========
    //          warps 8-15: store adjusted vcm
    if (w < 8) {
        const int qidx = 16 * w + (lane & 15);
        float qh_l = 0.f;
#pragma unroll
        for (int ww = 0; ww < 16; ww++) qh_l += sm[A_PB + ww * 132 + qidx];

        const float* Zt = g_fold + 384 * DD;
        float4 acc = make_float4(0.f, 0.f, 0.f, 0.f);
#pragma unroll
        for (int k = 0; k < 16; k++) {
            float q = __shfl_sync(0xffffffffu, qh_l, k);
            float4 zv = *(const float4*)(Zt + (size_t)(16 * w + k) * DD + c4);
            acc.x = fmaf(q, zv.x, acc.x);
            acc.y = fmaf(q, zv.y, acc.y);
            acc.z = fmaf(q, zv.z, acc.z);
            acc.w = fmaf(q, zv.w, acc.w);
        }
        float* gu = g_u + (size_t)b * 1024;
        gu[(c4 + 0) * 8 + w] = acc.x;
        gu[(c4 + 1) * 8 + w] = acc.y;
        gu[(c4 + 2) * 8 + w] = acc.z;
        gu[(c4 + 3) * 8 + w] = acc.w;
    } else {
        int c = t - 256;
        if (c < CC) g_vcmf[b * 104 + c] = sm[A_VCM + c];
    }
}

// ============================================================================
// Kernel 2b: smem compute back: scores, softmax, wsum, gv/gw (ZV/ZW),
// logits, outputs. grid = B, block = 512.
// ============================================================================
#define B_CS   0        // cluster tile [100][129]
#define B_U4   12900    // u packed [128][8]
#define B_SCP  13924    // score partials [100][16]
#define B_AT4  15524    // attn packed [100][8]
#define B_WS4  16324    // wsum packed [128][8]
#define B_PB   17348    // warp partials A [16][132]
#define B_PB2  19460    // warp partials B [16][132]
#define B_GW   21572
#define B_PART 21700    // [100][2] + pad
#define B_LGT  21908
#define B_MISC 22012
#define B_VCM  22014
#define B_FLOATS 22118
#define B_BYTES (B_FLOATS * 4)

__global__ void __launch_bounds__(512, 1)
clu_back_kernel(const float* __restrict__ depot, const float* __restrict__ cluster,
                const float* __restrict__ curE,
                const void* __restrict__ isnewp, const void* __restrict__ maskp,
                float* __restrict__ out) {
    extern __shared__ float sm[];
    const int b = blockIdx.x;
    const int t = threadIdx.x;
    const int lane = t & 31;
    const int w = t >> 5;
    const int c4 = lane * 4;

    const int flag = sniff_flag(maskp, t);
    const bool isnew = rdmask(isnewp, flag, b);

    // ===== L0: loads: cluster tile (L2-warm), u, vcm ========================
    {
        const float* cp = cluster + (size_t)b * CC * DD;
        for (int p4 = t; p4 < (CC * DD) / 4; p4 += 512) {
            float4 v = ((const float4*)cp)[p4];
            int base = p4 * 4;
            float* dst = sm + B_CS + (base >> 7) * 129 + (base & 127);
            dst[0] = v.x; dst[1] = v.y; dst[2] = v.z; dst[3] = v.w;
        }
    }
    if (t < 256) {
        float4 uv = ((const float4*)(g_u + (size_t)b * 1024))[t];
        *(float4*)(sm + B_U4 + t * 4) = uv;
    }
    if (t >= 256 && t < 256 + CC) {
        int c = t - 256;
        sm[B_VCM + c] = g_vcmf[b * 104 + c];
    }
    __syncthreads();

    // ===== P4: score partials (t<200: c, half) ==============================
    if (t < 2 * CC) {
        int c = t >> 1, half = t & 1, i0 = half * 64;
        float acc[8] = {0.f, 0.f, 0.f, 0.f, 0.f, 0.f, 0.f, 0.f};
#pragma unroll 4
        for (int i = i0; i < i0 + 64; i++) {
            float cv = sm[B_CS + c * 129 + i];
            float4 u0 = *(const float4*)(sm + B_U4 + i * 8);
            float4 u1 = *(const float4*)(sm + B_U4 + i * 8 + 4);
            acc[0] = fmaf(cv, u0.x, acc[0]);
            acc[1] = fmaf(cv, u0.y, acc[1]);
            acc[2] = fmaf(cv, u0.z, acc[2]);
            acc[3] = fmaf(cv, u0.w, acc[3]);
            acc[4] = fmaf(cv, u1.x, acc[4]);
            acc[5] = fmaf(cv, u1.y, acc[5]);
            acc[6] = fmaf(cv, u1.z, acc[6]);
            acc[7] = fmaf(cv, u1.w, acc[7]);
        }
#pragma unroll
        for (int h = 0; h < HH; h++) sm[B_SCP + c * 16 + half * 8 + h] = acc[h];
    }
    __syncthreads();

    // ===== P5: softmax — warp w (<8) handles head h=w ========================
    if (w < 8) {
        int h = w;
        float vv[4];
        float mx = -INFINITY;
#pragma unroll
        for (int idx = 0; idx < 4; idx++) {
            int c = lane + 32 * idx;
            float val = -INFINITY;
            if (c < CC) {
                float scv = sm[B_SCP + c * 16 + h] + sm[B_SCP + c * 16 + 8 + h];
                val = (sm[B_VCM + c] != 0.0f) ? NEGV : scv * 0.25f;
            }
            vv[idx] = val;
            mx = fmaxf(mx, val);
        }
#pragma unroll
        for (int off = 16; off; off >>= 1)
            mx = fmaxf(mx, __shfl_xor_sync(0xffffffffu, mx, off));
        float ssum = 0.f;
#pragma unroll
        for (int idx = 0; idx < 4; idx++) {
            int c = lane + 32 * idx;
            if (c < CC) {
                float e = expf(vv[idx] - mx);
                ssum += e;
                vv[idx] = e;
            }
        }
#pragma unroll
        for (int off = 16; off; off >>= 1)
            ssum += __shfl_xor_sync(0xffffffffu, ssum, off);
        float inv = 1.0f / ssum;
#pragma unroll
        for (int idx = 0; idx < 4; idx++) {
            int c = lane + 32 * idx;
            if (c < CC) sm[B_AT4 + c * 8 + h] = vv[idx] * inv;
        }
    }
    __syncthreads();

    // ===== P6: wsum[h][i] = sum_c attn[h][c]*cluster[c][i] (t<256) ===========
    if (t < 256) {
        int i = t & 127, par = t >> 7;
        float acc[4] = {0.f, 0.f, 0.f, 0.f};
#pragma unroll 4
        for (int c = 0; c < CC; c++) {
            float cv = sm[B_CS + c * 129 + i];
            float4 av = *(const float4*)(sm + B_AT4 + c * 8 + par * 4);
            acc[0] = fmaf(av.x, cv, acc[0]);
            acc[1] = fmaf(av.y, cv, acc[1]);
            acc[2] = fmaf(av.z, cv, acc[2]);
            acc[3] = fmaf(av.w, cv, acc[3]);
        }
        *(float4*)(sm + B_WS4 + i * 8 + par * 4) =
            make_float4(acc[0], acc[1], acc[2], acc[3]);
    }
    __syncthreads();

    // ===== P7: gv partials — warp w takes 8 rows of ZV (L2) ==================
    {
        const float* ZV = g_fold + 512 * DD;
        const int hsel = lane >> 2;
        float4 acc = make_float4(0.f, 0.f, 0.f, 0.f);
#pragma unroll
        for (int ii = 0; ii < 8; ii++) {
            int i = w * 8 + ii;
            float4 zv = *(const float4*)(ZV + (size_t)i * DD + c4);
            float s = sm[B_WS4 + i * 8 + hsel];
            acc.x = fmaf(s, zv.x, acc.x);
            acc.y = fmaf(s, zv.y, acc.y);
            acc.z = fmaf(s, zv.z, acc.z);
            acc.w = fmaf(s, zv.w, acc.w);
        }
        *(float4*)(sm + B_PB + w * 132 + c4) = acc;
    }
    __syncthreads();

    // ===== P9: warp-local GV reduce + gw partials from ZW (L2) ===============
    {
        const int gidx = 8 * w + (lane & 7);
        float gv_l = 0.f;
#pragma unroll
        for (int ww = 0; ww < 16; ww++) gv_l += sm[B_PB + ww * 132 + gidx];

        const float* ZW = g_fold + 640 * DD;
        float4 acc = make_float4(0.f, 0.f, 0.f, 0.f);
#pragma unroll
        for (int mm = 0; mm < 8; mm++) {
            float s = __shfl_sync(0xffffffffu, gv_l, mm);
            float4 zw = *(const float4*)(ZW + (size_t)(w * 8 + mm) * DD + c4);
            acc.x = fmaf(s, zw.x, acc.x);
            acc.y = fmaf(s, zw.y, acc.y);
            acc.z = fmaf(s, zw.z, acc.z);
            acc.w = fmaf(s, zw.w, acc.w);
        }
        *(float4*)(sm + B_PB2 + w * 132 + c4) = acc;
    }
    __syncthreads();

    // ===== P10: gw reduce ====================================================
    if (t < DD) {
        float s = 0.f;
#pragma unroll
        for (int ww = 0; ww < 16; ww++) s += sm[B_PB2 + ww * 132 + t];
        sm[B_GW + t] = s;
    }
    __syncthreads();

    // ===== P11: logit partials (t<200) =======================================
    if (t < 2 * CC) {
        int c = t >> 1, half = t & 1;
        float acc = 0.f;
        int i0 = half * 64;
#pragma unroll 8
        for (int i = i0; i < i0 + 64; i++)
            acc = fmaf(sm[B_CS + c * 129 + i], sm[B_GW + i], acc);
        sm[B_PART + c * 2 + half] = acc;
    }
    __syncthreads();

    // ===== P12: finalize logits + argmax + lse (warp 0) ======================
    if (w == 0) {
        float vv[4];
        float bv = -INFINITY;
        int bi = 0x7fffffff;
#pragma unroll
        for (int idx = 0; idx < 4; idx++) {
            int c = lane + 32 * idx;
            float val = -INFINITY;
            if (c < CC) {
                float lg = (sm[B_PART + c * 2] + sm[B_PART + c * 2 + 1])
                           * 0.08838834764831845f;
                lg = tanhf(lg) * CLIPV;
                val = (sm[B_VCM + c] != 0.0f) ? NEGV : lg;
                sm[B_LGT + c] = val;
                if (val > bv || (val == bv && c < bi)) { bv = val; bi = c; }
            }
            vv[idx] = val;
        }
#pragma unroll
        for (int off = 16; off; off >>= 1) {
            float ov = __shfl_down_sync(0xffffffffu, bv, off);
            int oi = __shfl_down_sync(0xffffffffu, bi, off);
            if (ov > bv || (ov == bv && oi < bi)) { bv = ov; bi = oi; }
        }
        bv = __shfl_sync(0xffffffffu, bv, 0);
        bi = __shfl_sync(0xffffffffu, bi, 0);
        float s = 0.f;
#pragma unroll
        for (int idx = 0; idx < 4; idx++) {
            int c = lane + 32 * idx;
            if (c < CC) s += expf(vv[idx] - bv);
        }
#pragma unroll
        for (int off = 16; off; off >>= 1) s += __shfl_xor_sync(0xffffffffu, s, off);
        if (lane == 0) {
            sm[B_MISC + 0] = (float)bi;
            sm[B_MISC + 1] = bv + logf(s);
        }
    }
    __syncthreads();

    // ===== P13: outputs ======================================================
    const int gid = (int)sm[B_MISC + 0];
    const float mlse = sm[B_MISC + 1];
    float* aug = out + OUT_AUG + (size_t)b * 512;
    float* gout = out + OUT_GEMB + (size_t)b * 128;
    float* cpo = out + OUT_CLU + (size_t)b * CC;
    if (t < DD) {
        float ge = sm[B_CS + gid * 129 + t];
        aug[t]        = isnew ? g_m2s[b * DD + t] : 0.0f;
        aug[128 + t]  = isnew ? curE[b * DD + t] : 0.0f;
        aug[256 + t]  = isnew ? ge : 0.0f;
        aug[384 + t]  = isnew ? depot[b * DD + t] : 0.0f;
        gout[t]       = isnew ? ge : 0.0f;
    }
    if (t >= 256 && t < 256 + CC) {
        int c = t - 256;
        cpo[c] = isnew ? (sm[B_LGT + c] - mlse) : 0.0f;
    }
    if (t == 511) out[OUT_GUID + b] = isnew ? (float)gid : 0.0f;
}

extern "C" void kernel_launch(void* const* d_in, const int* in_sizes, int n_in,
                              void* d_out, int out_size) {
    (void)in_sizes; (void)n_in; (void)out_size;
    const float* depot   = (const float*)d_in[0];
    const float* cluster = (const float*)d_in[1];
    const float* curE    = (const float*)d_in[2];
    const float* node    = (const float*)d_in[3];
    const void*  isnewp  = d_in[4];
    const void*  cmaskp  = d_in[5];
    const void*  vcmp    = d_in[6];
    const void*  maskp   = d_in[7];
    const float* Wq  = (const float*)d_in[8];
    const float* Wk  = (const float*)d_in[9];
    const float* Wv  = (const float*)d_in[10];
    const float* Wks = (const float*)d_in[11];
    const float* Wmq = (const float*)d_in[12];
    const float* Wmk = (const float*)d_in[13];
    const float* Wmv = (const float*)d_in[14];
    const float* Wmo = (const float*)d_in[15];

    means_pre_kernel<<<PRE_CTAS + BB * SPLIT, 256>>>(
        node, maskp, cmaskp, Wq, Wk, Wv, Wks, Wmq, Wmk, Wmv, Wmo);

    cudaFuncSetAttribute(clu_front_kernel,
                         cudaFuncAttributeMaxDynamicSharedMemorySize, A_BYTES);
    clu_front_kernel<<<BB, 512, A_BYTES>>>(
        depot, cluster, curE, isnewp, vcmp, maskp);

    cudaFuncSetAttribute(clu_back_kernel,
                         cudaFuncAttributeMaxDynamicSharedMemorySize, B_BYTES);
    clu_back_kernel<<<BB, 512, B_BYTES>>>(
        depot, cluster, curE, isnewp, maskp, (float*)d_out);
}